// round 1
// baseline (speedup 1.0000x reference)
#include <cuda_runtime.h>
#include <math.h>

#define N_TOK 131072
#define C_DIM 256
#define H_HEADS 8
#define D_HEAD 32
#define KBLK 128
#define NB (N_TOK / KBLK)
#define HID_DIM 1024
#define ATTN_SCALE 0.17677669529663687f   /* (C/H)^-0.5 = 32^-0.5 */
#define LN_EPS 1e-5f

// ---------------- scratch (device globals: allocation-free) ----------------
__device__ float g_x   [(size_t)N_TOK * C_DIM];      // LN1 out, reused for LN2 out
__device__ float g_qkv [(size_t)N_TOK * 3 * C_DIM];  // QKV
__device__ float g_attn[(size_t)N_TOK * C_DIM];      // attention output (un-permuted)
__device__ float g_x2  [(size_t)N_TOK * C_DIM];      // residual stream after attention
__device__ float g_h   [(size_t)N_TOK * HID_DIM];    // MLP hidden

// ---------------- LayerNorm: 1 warp per row (C=256) ----------------
__global__ __launch_bounds__(256) void ln_kernel(
    const float* __restrict__ in, const float* __restrict__ gamma,
    const float* __restrict__ beta, float* __restrict__ out)
{
    int row  = blockIdx.x * 8 + (threadIdx.x >> 5);
    int lane = threadIdx.x & 31;
    const float4* ip = (const float4*)(in + (size_t)row * C_DIM);
    float4 v0 = ip[lane];
    float4 v1 = ip[lane + 32];
    float sum = v0.x + v0.y + v0.z + v0.w + v1.x + v1.y + v1.z + v1.w;
    float sq  = v0.x*v0.x + v0.y*v0.y + v0.z*v0.z + v0.w*v0.w
              + v1.x*v1.x + v1.y*v1.y + v1.z*v1.z + v1.w*v1.w;
    #pragma unroll
    for (int o = 16; o; o >>= 1) {
        sum += __shfl_xor_sync(0xffffffffu, sum, o);
        sq  += __shfl_xor_sync(0xffffffffu, sq,  o);
    }
    float mu   = sum * (1.0f / 256.0f);
    float var  = sq * (1.0f / 256.0f) - mu * mu;
    float rstd = rsqrtf(var + LN_EPS);
    const float4* gp = (const float4*)gamma;
    const float4* bp = (const float4*)beta;
    float4 g0 = gp[lane], g1 = gp[lane + 32];
    float4 b0 = bp[lane], b1 = bp[lane + 32];
    float4 o0, o1;
    o0.x = (v0.x - mu) * rstd * g0.x + b0.x;
    o0.y = (v0.y - mu) * rstd * g0.y + b0.y;
    o0.z = (v0.z - mu) * rstd * g0.z + b0.z;
    o0.w = (v0.w - mu) * rstd * g0.w + b0.w;
    o1.x = (v1.x - mu) * rstd * g1.x + b1.x;
    o1.y = (v1.y - mu) * rstd * g1.y + b1.y;
    o1.z = (v1.z - mu) * rstd * g1.z + b1.z;
    o1.w = (v1.w - mu) * rstd * g1.w + b1.w;
    float4* op = (float4*)(out + (size_t)row * C_DIM);
    op[lane]      = o0;
    op[lane + 32] = o1;
}

// ---------------- SGEMM: C[M,Nc] = A[M,Kc] @ W[Nc,Kc]^T + bias (+epi) ------
// 128x128 tile, BK=8, 256 threads, 8x8 per thread.
enum { EPI_BIAS = 0, EPI_GELU = 1, EPI_RES = 2 };

__device__ __forceinline__ float gelu_exact(float x) {
    return 0.5f * x * (1.0f + erff(x * 0.7071067811865475f));
}

template<int EPI>
__global__ __launch_bounds__(256) void sgemm_kernel(
    const float* __restrict__ A, const float* __restrict__ W,
    const float* __restrict__ bias, const float* __restrict__ res,
    float* __restrict__ Cout, int M, int Nc, int Kc)
{
    __shared__ float As[8][128];
    __shared__ float Bs[8][128];
    const int tid = threadIdx.x;
    const int tx = tid & 15, ty = tid >> 4;
    const int bm = blockIdx.y * 128, bn = blockIdx.x * 128;
    const int lr = tid >> 1;
    const int lc = (tid & 1) * 4;
    const float* Ap = A + (size_t)(bm + lr) * Kc + lc;
    const float* Wp = W + (size_t)(bn + lr) * Kc + lc;

    float acc[8][8];
    #pragma unroll
    for (int i = 0; i < 8; i++)
        #pragma unroll
        for (int j = 0; j < 8; j++) acc[i][j] = 0.0f;

    for (int k0 = 0; k0 < Kc; k0 += 8) {
        float4 av = *(const float4*)(Ap + k0);
        float4 wv = *(const float4*)(Wp + k0);
        As[lc + 0][lr] = av.x; As[lc + 1][lr] = av.y;
        As[lc + 2][lr] = av.z; As[lc + 3][lr] = av.w;
        Bs[lc + 0][lr] = wv.x; Bs[lc + 1][lr] = wv.y;
        Bs[lc + 2][lr] = wv.z; Bs[lc + 3][lr] = wv.w;
        __syncthreads();
        #pragma unroll
        for (int kk = 0; kk < 8; kk++) {
            float4 a0 = *(const float4*)&As[kk][ty * 8];
            float4 a1 = *(const float4*)&As[kk][ty * 8 + 4];
            float4 b0 = *(const float4*)&Bs[kk][tx * 8];
            float4 b1 = *(const float4*)&Bs[kk][tx * 8 + 4];
            float ra[8] = {a0.x, a0.y, a0.z, a0.w, a1.x, a1.y, a1.z, a1.w};
            float rb[8] = {b0.x, b0.y, b0.z, b0.w, b1.x, b1.y, b1.z, b1.w};
            #pragma unroll
            for (int i = 0; i < 8; i++)
                #pragma unroll
                for (int j = 0; j < 8; j++)
                    acc[i][j] = fmaf(ra[i], rb[j], acc[i][j]);
        }
        __syncthreads();
    }

    #pragma unroll
    for (int i = 0; i < 8; i++) {
        int row = bm + ty * 8 + i;
        int col = bn + tx * 8;
        float* cp = Cout + (size_t)row * Nc + col;
        #pragma unroll
        for (int jj = 0; jj < 2; jj++) {
            float4 v;
            v.x = acc[i][jj * 4 + 0] + bias[col + jj * 4 + 0];
            v.y = acc[i][jj * 4 + 1] + bias[col + jj * 4 + 1];
            v.z = acc[i][jj * 4 + 2] + bias[col + jj * 4 + 2];
            v.w = acc[i][jj * 4 + 3] + bias[col + jj * 4 + 3];
            if (EPI == EPI_GELU) {
                v.x = gelu_exact(v.x); v.y = gelu_exact(v.y);
                v.z = gelu_exact(v.z); v.w = gelu_exact(v.w);
            } else if (EPI == EPI_RES) {
                float4 r = *(const float4*)(res + (size_t)row * Nc + col + jj * 4);
                v.x += r.x; v.y += r.y; v.z += r.z; v.w += r.w;
            }
            ((float4*)cp)[jj] = v;
        }
    }
}

// ---------------- Block attention: CTA per (block p, head h) ----------------
// Gathers q/k/v rows through `order`, scatters result through `order`.
__global__ __launch_bounds__(128) void attn_kernel(
    const float* __restrict__ qkv, const int* __restrict__ order,
    float* __restrict__ out)
{
    const int p = blockIdx.x;
    const int h = blockIdx.y;
    const int i = threadIdx.x;
    extern __shared__ float sm[];
    float* Ks = sm;                       // 128 * 32
    float* Vs = sm + 128 * 32;            // 128 * 32
    float* Ss = sm + 2 * 128 * 32;        // 128 * 129 (padded)

    int ord = order[p * KBLK + i];
    const float* rowp = qkv + (size_t)ord * (3 * C_DIM) + h * D_HEAD;

    float q[32];
    #pragma unroll
    for (int d4 = 0; d4 < 8; d4++) {
        float4 qv = ((const float4*)rowp)[d4];
        q[d4 * 4 + 0] = qv.x; q[d4 * 4 + 1] = qv.y;
        q[d4 * 4 + 2] = qv.z; q[d4 * 4 + 3] = qv.w;
        ((float4*)(Ks + i * 32))[d4] = ((const float4*)(rowp + C_DIM))[d4];
        ((float4*)(Vs + i * 32))[d4] = ((const float4*)(rowp + 2 * C_DIM))[d4];
    }
    __syncthreads();

    float* srow = Ss + i * 129;
    float m = -1e30f;
    for (int j = 0; j < 128; j++) {
        const float4* kp = (const float4*)(Ks + j * 32);
        float acc = 0.0f;
        #pragma unroll
        for (int d4 = 0; d4 < 8; d4++) {
            float4 kv = kp[d4];
            acc = fmaf(q[d4 * 4 + 0], kv.x, acc);
            acc = fmaf(q[d4 * 4 + 1], kv.y, acc);
            acc = fmaf(q[d4 * 4 + 2], kv.z, acc);
            acc = fmaf(q[d4 * 4 + 3], kv.w, acc);
        }
        acc *= ATTN_SCALE;
        srow[j] = acc;
        m = fmaxf(m, acc);
    }
    float l = 0.0f;
    for (int j = 0; j < 128; j++) {
        float e = __expf(srow[j] - m);
        srow[j] = e;
        l += e;
    }
    float inv = 1.0f / l;

    float o[32];
    #pragma unroll
    for (int d = 0; d < 32; d++) o[d] = 0.0f;
    for (int j = 0; j < 128; j++) {
        float pj = srow[j];
        const float4* vp = (const float4*)(Vs + j * 32);
        #pragma unroll
        for (int d4 = 0; d4 < 8; d4++) {
            float4 vv = vp[d4];
            o[d4 * 4 + 0] = fmaf(pj, vv.x, o[d4 * 4 + 0]);
            o[d4 * 4 + 1] = fmaf(pj, vv.y, o[d4 * 4 + 1]);
            o[d4 * 4 + 2] = fmaf(pj, vv.z, o[d4 * 4 + 2]);
            o[d4 * 4 + 3] = fmaf(pj, vv.w, o[d4 * 4 + 3]);
        }
    }

    float* op = out + (size_t)ord * C_DIM + h * D_HEAD;
    #pragma unroll
    for (int d4 = 0; d4 < 8; d4++) {
        float4 ov;
        ov.x = o[d4 * 4 + 0] * inv; ov.y = o[d4 * 4 + 1] * inv;
        ov.z = o[d4 * 4 + 2] * inv; ov.w = o[d4 * 4 + 3] * inv;
        ((float4*)op)[d4] = ov;
    }
}

// ---------------- launch ----------------
extern "C" void kernel_launch(void* const* d_in, const int* in_sizes, int n_in,
                              void* d_out, int out_size)
{
    const float* feat   = (const float*)d_in[0];
    const int*   order  = (const int*)  d_in[1];
    /* d_in[2] = inverse (unused: fused into scatter) */
    const float* qkv_w  = (const float*)d_in[3];
    const float* qkv_b  = (const float*)d_in[4];
    const float* proj_w = (const float*)d_in[5];
    const float* proj_b = (const float*)d_in[6];
    const float* ln1_g  = (const float*)d_in[7];
    const float* ln1_b  = (const float*)d_in[8];
    const float* ln2_g  = (const float*)d_in[9];
    const float* ln2_b  = (const float*)d_in[10];
    const float* w1     = (const float*)d_in[11];
    const float* b1     = (const float*)d_in[12];
    const float* w2     = (const float*)d_in[13];
    const float* b2     = (const float*)d_in[14];
    float* out = (float*)d_out;

    float *x, *qkvb, *attn, *x2, *hbuf;
    cudaGetSymbolAddress((void**)&x,    g_x);
    cudaGetSymbolAddress((void**)&qkvb, g_qkv);
    cudaGetSymbolAddress((void**)&attn, g_attn);
    cudaGetSymbolAddress((void**)&x2,   g_x2);
    cudaGetSymbolAddress((void**)&hbuf, g_h);

    const int attn_smem = (2 * 128 * 32 + 128 * 129) * sizeof(float); // 98816
    cudaFuncSetAttribute(attn_kernel,
                         cudaFuncAttributeMaxDynamicSharedMemorySize, attn_smem);

    // 1. LN1
    ln_kernel<<<N_TOK / 8, 256>>>(feat, ln1_g, ln1_b, x);
    // 2. QKV = x @ qkv_w^T + qkv_b
    sgemm_kernel<EPI_BIAS><<<dim3(6, N_TOK / 128), 256>>>(
        x, qkv_w, qkv_b, nullptr, qkvb, N_TOK, 3 * C_DIM, C_DIM);
    // 3. block attention (gather/scatter via order)
    attn_kernel<<<dim3(NB, H_HEADS), 128, attn_smem>>>(qkvb, order, attn);
    // 4. x2 = feat + attn @ proj_w^T + proj_b
    sgemm_kernel<EPI_RES><<<dim3(2, N_TOK / 128), 256>>>(
        attn, proj_w, proj_b, feat, x2, N_TOK, C_DIM, C_DIM);
    // 5. LN2 (into x, which is free now)
    ln_kernel<<<N_TOK / 8, 256>>>(x2, ln2_g, ln2_b, x);
    // 6. h = gelu(x @ w1^T + b1)
    sgemm_kernel<EPI_GELU><<<dim3(8, N_TOK / 128), 256>>>(
        x, w1, b1, nullptr, hbuf, N_TOK, HID_DIM, C_DIM);
    // 7. out = x2 + h @ w2^T + b2
    sgemm_kernel<EPI_RES><<<dim3(2, N_TOK / 128), 256>>>(
        hbuf, w2, b2, x2, out, N_TOK, C_DIM, HID_DIM);
}

// round 3
// speedup vs baseline: 3.2629x; 3.2629x over previous
#include <cuda_runtime.h>
#include <cuda_bf16.h>
#include <math.h>
#include <stdint.h>

#define N_TOK 131072
#define C_DIM 256
#define H_HEADS 8
#define D_HEAD 32
#define KBLK 128
#define NB (N_TOK / KBLK)
#define HID_DIM 1024
#define ATTN_SCALE 0.17677669529663687f
#define LN_EPS 1e-5f

// ---------------- scratch (device globals: allocation-free) ----------------
__device__ __nv_bfloat16 g_x   [(size_t)N_TOK * C_DIM];      // LN out (bf16)
__device__ __nv_bfloat16 g_qkv [(size_t)N_TOK * 3 * C_DIM];  // QKV (bf16)
__device__ __nv_bfloat16 g_attn[(size_t)N_TOK * C_DIM];      // attention out (bf16)
__device__ float         g_x2  [(size_t)N_TOK * C_DIM];      // residual stream (fp32)
__device__ __nv_bfloat16 g_h   [(size_t)N_TOK * HID_DIM];    // MLP hidden (bf16)
// bf16 weights
__device__ __nv_bfloat16 g_qkvw[3 * C_DIM * C_DIM];
__device__ __nv_bfloat16 g_projw[C_DIM * C_DIM];
__device__ __nv_bfloat16 g_w1  [HID_DIM * C_DIM];
__device__ __nv_bfloat16 g_w2  [C_DIM * HID_DIM];

// ======================= helpers =======================
__device__ __forceinline__ uint32_t smem_u32(const void* p) {
    uint32_t a;
    asm("{ .reg .u64 t; cvta.to.shared.u64 t, %1; cvt.u32.u64 %0, t; }" : "=r"(a) : "l"(p));
    return a;
}
__device__ __forceinline__ uint32_t sw128(uint32_t off) {
    return off ^ ((off >> 3) & 0x70);
}
__device__ __forceinline__ void cp_async16(uint32_t dst, const void* src) {
    asm volatile("cp.async.cg.shared.global [%0], [%1], 16;" :: "r"(dst), "l"(src));
}
#define CP_COMMIT() asm volatile("cp.async.commit_group;" ::: "memory")
#define CP_WAIT0()  asm volatile("cp.async.wait_group 0;" ::: "memory")
#define CP_WAIT1()  asm volatile("cp.async.wait_group 1;" ::: "memory")

__device__ __forceinline__ void ldsm_x4(uint32_t& r0, uint32_t& r1, uint32_t& r2, uint32_t& r3,
                                        uint32_t addr) {
    asm volatile("ldmatrix.sync.aligned.m8n8.x4.shared.b16 {%0,%1,%2,%3}, [%4];"
                 : "=r"(r0), "=r"(r1), "=r"(r2), "=r"(r3) : "r"(addr));
}
__device__ __forceinline__ void mma16816(float* d, const uint32_t* a, const uint32_t* b) {
    asm volatile("mma.sync.aligned.m16n8k16.row.col.f32.bf16.bf16.f32 "
                 "{%0,%1,%2,%3}, {%4,%5,%6,%7}, {%8,%9}, {%0,%1,%2,%3};"
                 : "+f"(d[0]), "+f"(d[1]), "+f"(d[2]), "+f"(d[3])
                 : "r"(a[0]), "r"(a[1]), "r"(a[2]), "r"(a[3]), "r"(b[0]), "r"(b[1]));
}

// ---------------- fp32 -> bf16 weight conversion ----------------
__global__ void cvt_kernel(const float* __restrict__ in, __nv_bfloat16* __restrict__ out, int n) {
    int i = blockIdx.x * blockDim.x + threadIdx.x;
    for (; i < n; i += gridDim.x * blockDim.x) out[i] = __float2bfloat16_rn(in[i]);
}

// ---------------- LayerNorm: 1 warp per row, bf16 out ----------------
__global__ __launch_bounds__(256) void ln_kernel(
    const float* __restrict__ in, const float* __restrict__ gamma,
    const float* __restrict__ beta, __nv_bfloat16* __restrict__ out)
{
    int row  = blockIdx.x * 8 + (threadIdx.x >> 5);
    int lane = threadIdx.x & 31;
    const float4* ip = (const float4*)(in + (size_t)row * C_DIM);
    float4 v0 = ip[lane];
    float4 v1 = ip[lane + 32];
    float sum = v0.x + v0.y + v0.z + v0.w + v1.x + v1.y + v1.z + v1.w;
    float sq  = v0.x*v0.x + v0.y*v0.y + v0.z*v0.z + v0.w*v0.w
              + v1.x*v1.x + v1.y*v1.y + v1.z*v1.z + v1.w*v1.w;
    #pragma unroll
    for (int o = 16; o; o >>= 1) {
        sum += __shfl_xor_sync(0xffffffffu, sum, o);
        sq  += __shfl_xor_sync(0xffffffffu, sq,  o);
    }
    float mu   = sum * (1.0f / 256.0f);
    float var  = sq * (1.0f / 256.0f) - mu * mu;
    float rstd = rsqrtf(var + LN_EPS);
    const float4* gp = (const float4*)gamma;
    const float4* bp = (const float4*)beta;
    float4 g0 = gp[lane], g1 = gp[lane + 32];
    float4 b0 = bp[lane], b1 = bp[lane + 32];
    float4 o0, o1;
    o0.x = (v0.x - mu) * rstd * g0.x + b0.x;
    o0.y = (v0.y - mu) * rstd * g0.y + b0.y;
    o0.z = (v0.z - mu) * rstd * g0.z + b0.z;
    o0.w = (v0.w - mu) * rstd * g0.w + b0.w;
    o1.x = (v1.x - mu) * rstd * g1.x + b1.x;
    o1.y = (v1.y - mu) * rstd * g1.y + b1.y;
    o1.z = (v1.z - mu) * rstd * g1.z + b1.z;
    o1.w = (v1.w - mu) * rstd * g1.w + b1.w;
    __nv_bfloat16* orow = out + (size_t)row * C_DIM;
    uint2 p0, p1;
    __nv_bfloat162 t;
    t = __floats2bfloat162_rn(o0.x, o0.y); p0.x = *(uint32_t*)&t;
    t = __floats2bfloat162_rn(o0.z, o0.w); p0.y = *(uint32_t*)&t;
    t = __floats2bfloat162_rn(o1.x, o1.y); p1.x = *(uint32_t*)&t;
    t = __floats2bfloat162_rn(o1.z, o1.w); p1.y = *(uint32_t*)&t;
    ((uint2*)orow)[lane]      = p0;
    ((uint2*)orow)[lane + 32] = p1;
}

// ================= HMMA bf16 GEMM (mma.sync m16n8k16) =================
// D[M,Nc] = A[M,Kc]_bf16 @ W[Nc,Kc]_bf16^T + bias (+epilogue)
// CTA 128x128, BK=64, cp.async double buffer, 8 warps (2x4), warp tile 64x32.
enum { EPI_BIAS = 0, EPI_GELU = 1, EPI_RES = 2 };

__device__ __forceinline__ float gelu_exact(float x) {
    return 0.5f * x * (1.0f + erff(x * 0.7071067811865475f));
}

#define SA0 0
#define SA1 16384
#define SB0 32768
#define SB1 49152
#define GEMM_SMEM 65536

template<int EPI, typename OutT, int KC>
__global__ __launch_bounds__(256, 2) void mma_gemm_kernel(
    const __nv_bfloat16* __restrict__ A, const __nv_bfloat16* __restrict__ W,
    const float* __restrict__ bias, const float* __restrict__ res,
    OutT* __restrict__ Cout, int Nc)
{
    extern __shared__ char smem[];
    const uint32_t sbase = smem_u32(smem);
    const int tid = threadIdx.x;
    const int wid = tid >> 5;
    const int lid = tid & 31;
    const int wm = wid >> 2;          // 0..1  (64 rows each)
    const int wn = wid & 3;           // 0..3  (32 cols each)
    const int bm = blockIdx.y * 128;
    const int bn = blockIdx.x * 128;
    const int NCH = KC / 64;

    float acc[4][4][4];
    #pragma unroll
    for (int i = 0; i < 4; i++)
        #pragma unroll
        for (int j = 0; j < 4; j++)
            #pragma unroll
            for (int e = 0; e < 4; e++) acc[i][j][e] = 0.0f;

    // global load positions: 1024 16B-chunks per tile, 4 per thread
    const int lr = tid >> 1;              // 0..127 (row), two threads per row
    const int lc0 = (tid & 1) * 4;        // chunk 0..7 split: this thread does lc0..lc0+3
    const __nv_bfloat16* Arow = A + (size_t)(bm + lr) * KC;
    const __nv_bfloat16* Wrow = W + (size_t)(bn + lr) * KC;

    auto load_tile = [&](int c, int buf) {
        uint32_t dA = sbase + (buf ? SA1 : SA0);
        uint32_t dB = sbase + (buf ? SB1 : SB0);
        const __nv_bfloat16* as = Arow + c * 64 + lc0 * 8;
        const __nv_bfloat16* ws = Wrow + c * 64 + lc0 * 8;
        #pragma unroll
        for (int q = 0; q < 4; q++) {
            uint32_t off = sw128(lr * 128 + (lc0 + q) * 16);
            cp_async16(dA + off, as + q * 8);
            cp_async16(dB + off, ws + q * 8);
        }
    };

    load_tile(0, 0);
    CP_COMMIT();

    for (int c = 0; c < NCH; c++) {
        const int buf = c & 1;
        if (c + 1 < NCH) {
            load_tile(c + 1, buf ^ 1);
            CP_COMMIT();
            CP_WAIT1();
        } else {
            CP_WAIT0();
        }
        __syncthreads();

        const uint32_t sA = sbase + (buf ? SA1 : SA0);
        const uint32_t sB = sbase + (buf ? SB1 : SB0);
        #pragma unroll
        for (int kk = 0; kk < 4; kk++) {
            const uint32_t kbyte = kk * 32 + (lid >> 4) * 16;
            uint32_t af[4][4];
            #pragma unroll
            for (int mt = 0; mt < 4; mt++) {
                uint32_t row = wm * 64 + mt * 16 + (lid & 15);
                ldsm_x4(af[mt][0], af[mt][1], af[mt][2], af[mt][3],
                        sA + sw128(row * 128 + kbyte));
            }
            uint32_t bf[4][2];
            #pragma unroll
            for (int np = 0; np < 2; np++) {
                uint32_t r0, r1, r2, r3;
                uint32_t row = wn * 32 + np * 16 + (lid & 15);
                ldsm_x4(r0, r1, r2, r3, sB + sw128(row * 128 + kbyte));
                bf[np * 2 + 0][0] = r0; bf[np * 2 + 0][1] = r2;
                bf[np * 2 + 1][0] = r1; bf[np * 2 + 1][1] = r3;
            }
            #pragma unroll
            for (int mt = 0; mt < 4; mt++)
                #pragma unroll
                for (int nt = 0; nt < 4; nt++)
                    mma16816(acc[mt][nt], af[mt], bf[nt]);
        }
        __syncthreads();
    }

    // ---------------- epilogue ----------------
    // thread owns, per (mt,nt): rows r,r+8 (r=lane>>2), cols c,c+1 (c=(lane&3)*2)
    float bv[4][2];
    #pragma unroll
    for (int nt = 0; nt < 4; nt++) {
        int col = bn + wn * 32 + nt * 8 + (lid & 3) * 2;
        bv[nt][0] = bias[col];
        bv[nt][1] = bias[col + 1];
    }

    #pragma unroll
    for (int mt = 0; mt < 4; mt++) {
        #pragma unroll
        for (int half = 0; half < 2; half++) {
            int row = bm + wm * 64 + mt * 16 + (lid >> 2) + half * 8;
            #pragma unroll
            for (int nt = 0; nt < 4; nt++) {
                int col = bn + wn * 32 + nt * 8 + (lid & 3) * 2;
                float v0 = acc[mt][nt][half * 2 + 0] + bv[nt][0];
                float v1 = acc[mt][nt][half * 2 + 1] + bv[nt][1];
                if (EPI == EPI_GELU) {
                    v0 = gelu_exact(v0);
                    v1 = gelu_exact(v1);
                } else if (EPI == EPI_RES) {
                    float2 rv = *(const float2*)(res + (size_t)row * Nc + col);
                    v0 += rv.x; v1 += rv.y;
                }
                if (sizeof(OutT) == 4) {
                    float2 ov = make_float2(v0, v1);
                    *(float2*)((float*)Cout + (size_t)row * Nc + col) = ov;
                } else {
                    __nv_bfloat162 t = __floats2bfloat162_rn(v0, v1);
                    *(uint32_t*)((__nv_bfloat16*)Cout + (size_t)row * Nc + col) =
                        *(uint32_t*)&t;
                }
            }
        }
    }
}

// ---------------- Block attention: CTA per (block p, head h), bf16 I/O ------
__global__ __launch_bounds__(128) void attn_kernel(
    const __nv_bfloat16* __restrict__ qkv, const int* __restrict__ order,
    __nv_bfloat16* __restrict__ out)
{
    const int p = blockIdx.x;
    const int h = blockIdx.y;
    const int i = threadIdx.x;
    extern __shared__ float sm[];
    float* Ks = sm;                       // 128 * 32
    float* Vs = sm + 128 * 32;            // 128 * 32
    float* Ss = sm + 2 * 128 * 32;        // 128 * 129

    int ord = order[p * KBLK + i];
    const __nv_bfloat16* rowp = qkv + (size_t)ord * (3 * C_DIM) + h * D_HEAD;

    float q[32];
    #pragma unroll
    for (int u = 0; u < 4; u++) {
        uint4 tq = ((const uint4*)rowp)[u];
        uint4 tk = ((const uint4*)(rowp + C_DIM))[u];
        uint4 tv = ((const uint4*)(rowp + 2 * C_DIM))[u];
        const uint32_t* qa = &tq.x;
        const uint32_t* ka = &tk.x;
        const uint32_t* va = &tv.x;
        #pragma unroll
        for (int e = 0; e < 4; e++) {
            float2 f;
            f = __bfloat1622float2(*(const __nv_bfloat162*)&qa[e]);
            q[u * 8 + e * 2] = f.x; q[u * 8 + e * 2 + 1] = f.y;
            f = __bfloat1622float2(*(const __nv_bfloat162*)&ka[e]);
            Ks[i * 32 + u * 8 + e * 2] = f.x; Ks[i * 32 + u * 8 + e * 2 + 1] = f.y;
            f = __bfloat1622float2(*(const __nv_bfloat162*)&va[e]);
            Vs[i * 32 + u * 8 + e * 2] = f.x; Vs[i * 32 + u * 8 + e * 2 + 1] = f.y;
        }
    }
    __syncthreads();

    float* srow = Ss + i * 129;
    float m = -1e30f;
    for (int j = 0; j < 128; j++) {
        const float4* kp = (const float4*)(Ks + j * 32);
        float acc = 0.0f;
        #pragma unroll
        for (int d4 = 0; d4 < 8; d4++) {
            float4 kv = kp[d4];
            acc = fmaf(q[d4 * 4 + 0], kv.x, acc);
            acc = fmaf(q[d4 * 4 + 1], kv.y, acc);
            acc = fmaf(q[d4 * 4 + 2], kv.z, acc);
            acc = fmaf(q[d4 * 4 + 3], kv.w, acc);
        }
        acc *= ATTN_SCALE;
        srow[j] = acc;
        m = fmaxf(m, acc);
    }
    float l = 0.0f;
    for (int j = 0; j < 128; j++) {
        float e = __expf(srow[j] - m);
        srow[j] = e;
        l += e;
    }
    float inv = 1.0f / l;

    float o[32];
    #pragma unroll
    for (int d = 0; d < 32; d++) o[d] = 0.0f;
    for (int j = 0; j < 128; j++) {
        float pj = srow[j];
        const float4* vp = (const float4*)(Vs + j * 32);
        #pragma unroll
        for (int d4 = 0; d4 < 8; d4++) {
            float4 vv = vp[d4];
            o[d4 * 4 + 0] = fmaf(pj, vv.x, o[d4 * 4 + 0]);
            o[d4 * 4 + 1] = fmaf(pj, vv.y, o[d4 * 4 + 1]);
            o[d4 * 4 + 2] = fmaf(pj, vv.z, o[d4 * 4 + 2]);
            o[d4 * 4 + 3] = fmaf(pj, vv.w, o[d4 * 4 + 3]);
        }
    }

    __nv_bfloat16* op = out + (size_t)ord * C_DIM + h * D_HEAD;
    uint32_t w[16];
    #pragma unroll
    for (int j2 = 0; j2 < 16; j2++) {
        __nv_bfloat162 t = __floats2bfloat162_rn(o[j2 * 2] * inv, o[j2 * 2 + 1] * inv);
        w[j2] = *(uint32_t*)&t;
    }
    #pragma unroll
    for (int qd = 0; qd < 4; qd++)
        ((uint4*)op)[qd] = make_uint4(w[qd*4+0], w[qd*4+1], w[qd*4+2], w[qd*4+3]);
}

// ---------------- launch ----------------
extern "C" void kernel_launch(void* const* d_in, const int* in_sizes, int n_in,
                              void* d_out, int out_size)
{
    const float* feat   = (const float*)d_in[0];
    const int*   order  = (const int*)  d_in[1];
    const float* qkv_w  = (const float*)d_in[3];
    const float* qkv_b  = (const float*)d_in[4];
    const float* proj_w = (const float*)d_in[5];
    const float* proj_b = (const float*)d_in[6];
    const float* ln1_g  = (const float*)d_in[7];
    const float* ln1_b  = (const float*)d_in[8];
    const float* ln2_g  = (const float*)d_in[9];
    const float* ln2_b  = (const float*)d_in[10];
    const float* w1     = (const float*)d_in[11];
    const float* b1     = (const float*)d_in[12];
    const float* w2     = (const float*)d_in[13];
    const float* b2     = (const float*)d_in[14];
    float* out = (float*)d_out;

    __nv_bfloat16 *x, *qkvb, *attn, *hbuf, *qkvw, *projw, *w1b, *w2b;
    float *x2;
    cudaGetSymbolAddress((void**)&x,     g_x);
    cudaGetSymbolAddress((void**)&qkvb,  g_qkv);
    cudaGetSymbolAddress((void**)&attn,  g_attn);
    cudaGetSymbolAddress((void**)&x2,    g_x2);
    cudaGetSymbolAddress((void**)&hbuf,  g_h);
    cudaGetSymbolAddress((void**)&qkvw,  g_qkvw);
    cudaGetSymbolAddress((void**)&projw, g_projw);
    cudaGetSymbolAddress((void**)&w1b,   g_w1);
    cudaGetSymbolAddress((void**)&w2b,   g_w2);

    const int attn_smem = (2 * 128 * 32 + 128 * 129) * sizeof(float); // 98816
    cudaFuncSetAttribute(attn_kernel,
                         cudaFuncAttributeMaxDynamicSharedMemorySize, attn_smem);
    cudaFuncSetAttribute(mma_gemm_kernel<EPI_BIAS, __nv_bfloat16, 256>,
                         cudaFuncAttributeMaxDynamicSharedMemorySize, GEMM_SMEM);
    cudaFuncSetAttribute(mma_gemm_kernel<EPI_RES, float, 256>,
                         cudaFuncAttributeMaxDynamicSharedMemorySize, GEMM_SMEM);
    cudaFuncSetAttribute(mma_gemm_kernel<EPI_GELU, __nv_bfloat16, 256>,
                         cudaFuncAttributeMaxDynamicSharedMemorySize, GEMM_SMEM);
    cudaFuncSetAttribute(mma_gemm_kernel<EPI_RES, float, 1024>,
                         cudaFuncAttributeMaxDynamicSharedMemorySize, GEMM_SMEM);

    // 0. weights fp32 -> bf16
    cvt_kernel<<<192, 256>>>(qkv_w,  qkvw, 3 * C_DIM * C_DIM);
    cvt_kernel<<<64, 256>>>(proj_w, projw, C_DIM * C_DIM);
    cvt_kernel<<<256, 256>>>(w1,    w1b,  HID_DIM * C_DIM);
    cvt_kernel<<<256, 256>>>(w2,    w2b,  C_DIM * HID_DIM);

    // 1. LN1 -> bf16
    ln_kernel<<<N_TOK / 8, 256>>>(feat, ln1_g, ln1_b, x);
    // 2. QKV = x @ qkv_w^T + qkv_b  (bf16 out)
    mma_gemm_kernel<EPI_BIAS, __nv_bfloat16, 256><<<dim3(6, N_TOK / 128), 256, GEMM_SMEM>>>(
        x, qkvw, qkv_b, nullptr, qkvb, 3 * C_DIM);
    // 3. block attention (gather/scatter via order), bf16 out
    attn_kernel<<<dim3(NB, H_HEADS), 128, attn_smem>>>(qkvb, order, attn);
    // 4. x2 = feat + attn @ proj_w^T + proj_b   (fp32 out)
    mma_gemm_kernel<EPI_RES, float, 256><<<dim3(2, N_TOK / 128), 256, GEMM_SMEM>>>(
        attn, projw, proj_b, feat, x2, C_DIM);
    // 5. LN2 -> bf16 (reuse x)
    ln_kernel<<<N_TOK / 8, 256>>>(x2, ln2_g, ln2_b, x);
    // 6. h = gelu(x @ w1^T + b1)  (bf16 out)
    mma_gemm_kernel<EPI_GELU, __nv_bfloat16, 256><<<dim3(8, N_TOK / 128), 256, GEMM_SMEM>>>(
        x, w1b, b1, nullptr, hbuf, HID_DIM);
    // 7. out = x2 + h @ w2^T + b2  (fp32 out)
    mma_gemm_kernel<EPI_RES, float, 1024><<<dim3(2, N_TOK / 128), 256, GEMM_SMEM>>>(
        hbuf, w2b, b2, x2, out, C_DIM);
}

// round 4
// speedup vs baseline: 5.0314x; 1.5420x over previous
#include <cuda_runtime.h>
#include <cuda_bf16.h>
#include <math.h>
#include <stdint.h>

#define N_TOK 131072
#define C_DIM 256
#define H_HEADS 8
#define D_HEAD 32
#define KBLK 128
#define NB (N_TOK / KBLK)
#define HID_DIM 1024
#define ATTN_SCALE 0.17677669529663687f
#define LN_EPS 1e-5f

// ---------------- scratch (device globals: allocation-free) ----------------
__device__ __nv_bfloat16 g_x   [(size_t)N_TOK * C_DIM];      // LN out (bf16)
__device__ __nv_bfloat16 g_qkv [(size_t)N_TOK * 3 * C_DIM];  // QKV (bf16)
__device__ __nv_bfloat16 g_attn[(size_t)N_TOK * C_DIM];      // attention out (bf16)
__device__ float         g_x2  [(size_t)N_TOK * C_DIM];      // residual stream (fp32)
__device__ __nv_bfloat16 g_h   [(size_t)N_TOK * HID_DIM];    // MLP hidden (bf16)
// bf16 weights
__device__ __nv_bfloat16 g_qkvw[3 * C_DIM * C_DIM];
__device__ __nv_bfloat16 g_projw[C_DIM * C_DIM];
__device__ __nv_bfloat16 g_w1  [HID_DIM * C_DIM];
__device__ __nv_bfloat16 g_w2  [C_DIM * HID_DIM];

// ======================= helpers =======================
__device__ __forceinline__ uint32_t smem_u32(const void* p) {
    uint32_t a;
    asm("{ .reg .u64 t; cvta.to.shared.u64 t, %1; cvt.u32.u64 %0, t; }" : "=r"(a) : "l"(p));
    return a;
}
__device__ __forceinline__ uint32_t sw128(uint32_t off) {
    return off ^ ((off >> 3) & 0x70);
}
__device__ __forceinline__ void cp_async16(uint32_t dst, const void* src) {
    asm volatile("cp.async.cg.shared.global [%0], [%1], 16;" :: "r"(dst), "l"(src));
}
#define CP_COMMIT() asm volatile("cp.async.commit_group;" ::: "memory")
#define CP_WAIT0()  asm volatile("cp.async.wait_group 0;" ::: "memory")
#define CP_WAIT1()  asm volatile("cp.async.wait_group 1;" ::: "memory")

__device__ __forceinline__ void ldsm_x4(uint32_t& r0, uint32_t& r1, uint32_t& r2, uint32_t& r3,
                                        uint32_t addr) {
    asm volatile("ldmatrix.sync.aligned.m8n8.x4.shared.b16 {%0,%1,%2,%3}, [%4];"
                 : "=r"(r0), "=r"(r1), "=r"(r2), "=r"(r3) : "r"(addr));
}
__device__ __forceinline__ void ldsm_x4_t(uint32_t& r0, uint32_t& r1, uint32_t& r2, uint32_t& r3,
                                          uint32_t addr) {
    asm volatile("ldmatrix.sync.aligned.m8n8.x4.trans.shared.b16 {%0,%1,%2,%3}, [%4];"
                 : "=r"(r0), "=r"(r1), "=r"(r2), "=r"(r3) : "r"(addr));
}
__device__ __forceinline__ void mma16816(float* d, const uint32_t* a, const uint32_t* b) {
    asm volatile("mma.sync.aligned.m16n8k16.row.col.f32.bf16.bf16.f32 "
                 "{%0,%1,%2,%3}, {%4,%5,%6,%7}, {%8,%9}, {%0,%1,%2,%3};"
                 : "+f"(d[0]), "+f"(d[1]), "+f"(d[2]), "+f"(d[3])
                 : "r"(a[0]), "r"(a[1]), "r"(a[2]), "r"(a[3]), "r"(b[0]), "r"(b[1]));
}
__device__ __forceinline__ uint32_t packbf2(float a, float b) {
    __nv_bfloat162 t = __floats2bfloat162_rn(a, b);
    return *(uint32_t*)&t;
}

// ---------------- fp32 -> bf16 weight conversion (all 4 in one) ------------
__global__ void cvt_all_kernel(
    const float* __restrict__ s0, __nv_bfloat16* __restrict__ d0, int n0,
    const float* __restrict__ s1, __nv_bfloat16* __restrict__ d1, int n1,
    const float* __restrict__ s2, __nv_bfloat16* __restrict__ d2, int n2,
    const float* __restrict__ s3, __nv_bfloat16* __restrict__ d3, int n3)
{
    int total = n0 + n1 + n2 + n3;
    for (int i = blockIdx.x * blockDim.x + threadIdx.x; i < total;
         i += gridDim.x * blockDim.x) {
        int j = i;
        if (j < n0) { d0[j] = __float2bfloat16_rn(s0[j]); continue; }
        j -= n0;
        if (j < n1) { d1[j] = __float2bfloat16_rn(s1[j]); continue; }
        j -= n1;
        if (j < n2) { d2[j] = __float2bfloat16_rn(s2[j]); continue; }
        j -= n2;
        d3[j] = __float2bfloat16_rn(s3[j]);
    }
}

// ---------------- LayerNorm: 1 warp per row, bf16 out ----------------
__global__ __launch_bounds__(256) void ln_kernel(
    const float* __restrict__ in, const float* __restrict__ gamma,
    const float* __restrict__ beta, __nv_bfloat16* __restrict__ out)
{
    int row  = blockIdx.x * 8 + (threadIdx.x >> 5);
    int lane = threadIdx.x & 31;
    const float4* ip = (const float4*)(in + (size_t)row * C_DIM);
    float4 v0 = ip[lane];
    float4 v1 = ip[lane + 32];
    float sum = v0.x + v0.y + v0.z + v0.w + v1.x + v1.y + v1.z + v1.w;
    float sq  = v0.x*v0.x + v0.y*v0.y + v0.z*v0.z + v0.w*v0.w
              + v1.x*v1.x + v1.y*v1.y + v1.z*v1.z + v1.w*v1.w;
    #pragma unroll
    for (int o = 16; o; o >>= 1) {
        sum += __shfl_xor_sync(0xffffffffu, sum, o);
        sq  += __shfl_xor_sync(0xffffffffu, sq,  o);
    }
    float mu   = sum * (1.0f / 256.0f);
    float var  = sq * (1.0f / 256.0f) - mu * mu;
    float rstd = rsqrtf(var + LN_EPS);
    const float4* gp = (const float4*)gamma;
    const float4* bp = (const float4*)beta;
    float4 g0 = gp[lane], g1 = gp[lane + 32];
    float4 b0 = bp[lane], b1 = bp[lane + 32];
    float4 o0, o1;
    o0.x = (v0.x - mu) * rstd * g0.x + b0.x;
    o0.y = (v0.y - mu) * rstd * g0.y + b0.y;
    o0.z = (v0.z - mu) * rstd * g0.z + b0.z;
    o0.w = (v0.w - mu) * rstd * g0.w + b0.w;
    o1.x = (v1.x - mu) * rstd * g1.x + b1.x;
    o1.y = (v1.y - mu) * rstd * g1.y + b1.y;
    o1.z = (v1.z - mu) * rstd * g1.z + b1.z;
    o1.w = (v1.w - mu) * rstd * g1.w + b1.w;
    __nv_bfloat16* orow = out + (size_t)row * C_DIM;
    uint2 p0, p1;
    p0.x = packbf2(o0.x, o0.y); p0.y = packbf2(o0.z, o0.w);
    p1.x = packbf2(o1.x, o1.y); p1.y = packbf2(o1.z, o1.w);
    ((uint2*)orow)[lane]      = p0;
    ((uint2*)orow)[lane + 32] = p1;
}

// ================= HMMA bf16 GEMM (mma.sync m16n8k16) =================
enum { EPI_BIAS = 0, EPI_GELU = 1, EPI_RES = 2 };

__device__ __forceinline__ float gelu_exact(float x) {
    return 0.5f * x * (1.0f + erff(x * 0.7071067811865475f));
}

#define SA0 0
#define SA1 16384
#define SB0 32768
#define SB1 49152
#define GEMM_SMEM 65536

template<int EPI, typename OutT, int KC>
__global__ __launch_bounds__(256, 2) void mma_gemm_kernel(
    const __nv_bfloat16* __restrict__ A, const __nv_bfloat16* __restrict__ W,
    const float* __restrict__ bias, const float* __restrict__ res,
    OutT* __restrict__ Cout, int Nc)
{
    extern __shared__ char smem[];
    const uint32_t sbase = smem_u32(smem);
    const int tid = threadIdx.x;
    const int wid = tid >> 5;
    const int lid = tid & 31;
    const int wm = wid >> 2;
    const int wn = wid & 3;
    const int bm = blockIdx.y * 128;
    const int bn = blockIdx.x * 128;
    const int NCH = KC / 64;

    float acc[4][4][4];
    #pragma unroll
    for (int i = 0; i < 4; i++)
        #pragma unroll
        for (int j = 0; j < 4; j++)
            #pragma unroll
            for (int e = 0; e < 4; e++) acc[i][j][e] = 0.0f;

    const int lr = tid >> 1;
    const int lc0 = (tid & 1) * 4;
    const __nv_bfloat16* Arow = A + (size_t)(bm + lr) * KC;
    const __nv_bfloat16* Wrow = W + (size_t)(bn + lr) * KC;

    auto load_tile = [&](int c, int buf) {
        uint32_t dA = sbase + (buf ? SA1 : SA0);
        uint32_t dB = sbase + (buf ? SB1 : SB0);
        const __nv_bfloat16* as = Arow + c * 64 + lc0 * 8;
        const __nv_bfloat16* ws = Wrow + c * 64 + lc0 * 8;
        #pragma unroll
        for (int q = 0; q < 4; q++) {
            uint32_t off = sw128(lr * 128 + (lc0 + q) * 16);
            cp_async16(dA + off, as + q * 8);
            cp_async16(dB + off, ws + q * 8);
        }
    };

    load_tile(0, 0);
    CP_COMMIT();

    for (int c = 0; c < NCH; c++) {
        const int buf = c & 1;
        if (c + 1 < NCH) {
            load_tile(c + 1, buf ^ 1);
            CP_COMMIT();
            CP_WAIT1();
        } else {
            CP_WAIT0();
        }
        __syncthreads();

        const uint32_t sA = sbase + (buf ? SA1 : SA0);
        const uint32_t sB = sbase + (buf ? SB1 : SB0);
        #pragma unroll
        for (int kk = 0; kk < 4; kk++) {
            const uint32_t kbyte = kk * 32 + (lid >> 4) * 16;
            uint32_t af[4][4];
            #pragma unroll
            for (int mt = 0; mt < 4; mt++) {
                uint32_t row = wm * 64 + mt * 16 + (lid & 15);
                ldsm_x4(af[mt][0], af[mt][1], af[mt][2], af[mt][3],
                        sA + sw128(row * 128 + kbyte));
            }
            uint32_t bf[4][2];
            #pragma unroll
            for (int np = 0; np < 2; np++) {
                uint32_t r0, r1, r2, r3;
                uint32_t row = wn * 32 + np * 16 + (lid & 15);
                ldsm_x4(r0, r1, r2, r3, sB + sw128(row * 128 + kbyte));
                bf[np * 2 + 0][0] = r0; bf[np * 2 + 0][1] = r2;
                bf[np * 2 + 1][0] = r1; bf[np * 2 + 1][1] = r3;
            }
            #pragma unroll
            for (int mt = 0; mt < 4; mt++)
                #pragma unroll
                for (int nt = 0; nt < 4; nt++)
                    mma16816(acc[mt][nt], af[mt], bf[nt]);
        }
        __syncthreads();
    }

    float bv[4][2];
    #pragma unroll
    for (int nt = 0; nt < 4; nt++) {
        int col = bn + wn * 32 + nt * 8 + (lid & 3) * 2;
        bv[nt][0] = bias[col];
        bv[nt][1] = bias[col + 1];
    }

    #pragma unroll
    for (int mt = 0; mt < 4; mt++) {
        #pragma unroll
        for (int half = 0; half < 2; half++) {
            int row = bm + wm * 64 + mt * 16 + (lid >> 2) + half * 8;
            #pragma unroll
            for (int nt = 0; nt < 4; nt++) {
                int col = bn + wn * 32 + nt * 8 + (lid & 3) * 2;
                float v0 = acc[mt][nt][half * 2 + 0] + bv[nt][0];
                float v1 = acc[mt][nt][half * 2 + 1] + bv[nt][1];
                if (EPI == EPI_GELU) {
                    v0 = gelu_exact(v0);
                    v1 = gelu_exact(v1);
                } else if (EPI == EPI_RES) {
                    float2 rv = *(const float2*)(res + (size_t)row * Nc + col);
                    v0 += rv.x; v1 += rv.y;
                }
                if (sizeof(OutT) == 4) {
                    float2 ov = make_float2(v0, v1);
                    *(float2*)((float*)Cout + (size_t)row * Nc + col) = ov;
                } else {
                    *(uint32_t*)((__nv_bfloat16*)Cout + (size_t)row * Nc + col) =
                        packbf2(v0, v1);
                }
            }
        }
    }
}

// ================= HMMA block attention =================
// CTA per (block p, head h). 256 threads / 8 warps; warp w owns score rows
// [16w, 16w+16). S = Q K^T via mma (K non-trans as [n][k]); softmax in regs;
// P @ V reuses S accumulators as A-fragments; V via ldmatrix.trans.
#define ATT_STRIDE 40   /* bf16 elements per row: 32 data + 8 pad (80 B) */

__global__ __launch_bounds__(256) void attn_mma_kernel(
    const __nv_bfloat16* __restrict__ qkv, const int* __restrict__ order,
    __nv_bfloat16* __restrict__ out)
{
    __shared__ __nv_bfloat16 Qs[128 * ATT_STRIDE];
    __shared__ __nv_bfloat16 Ks[128 * ATT_STRIDE];
    __shared__ __nv_bfloat16 Vs[128 * ATT_STRIDE];

    const int p   = blockIdx.x;
    const int h   = blockIdx.y;
    const int tid = threadIdx.x;
    const int wid = tid >> 5;
    const int lid = tid & 31;

    // ---- gather q/k/v rows (bf16) via cp.async ----
    {
        const int row  = tid >> 1;        // 0..127
        const int half = tid & 1;         // bytes [0,32) or [32,64)
        int ord = order[p * KBLK + row];
        const __nv_bfloat16* base = qkv + (size_t)ord * (3 * C_DIM) + h * D_HEAD;
        uint32_t dq = smem_u32(Qs) + row * 80 + half * 32;
        uint32_t dk = smem_u32(Ks) + row * 80 + half * 32;
        uint32_t dv = smem_u32(Vs) + row * 80 + half * 32;
        const __nv_bfloat16* sq = base + half * 16;
        cp_async16(dq,      sq);
        cp_async16(dq + 16, sq + 8);
        cp_async16(dk,      sq + C_DIM);
        cp_async16(dk + 16, sq + C_DIM + 8);
        cp_async16(dv,      sq + 2 * C_DIM);
        cp_async16(dv + 16, sq + 2 * C_DIM + 8);
    }
    CP_COMMIT();
    CP_WAIT0();
    __syncthreads();

    const uint32_t qb = smem_u32(Qs);
    const uint32_t kb = smem_u32(Ks);
    const uint32_t vb = smem_u32(Vs);
    const int m0 = wid * 16;

    // ---- S = Q K^T ----
    uint32_t aq[2][4];
    #pragma unroll
    for (int ks = 0; ks < 2; ks++)
        ldsm_x4(aq[ks][0], aq[ks][1], aq[ks][2], aq[ks][3],
                qb + (m0 + (lid & 15)) * 80 + ks * 32 + (lid >> 4) * 16);

    float accS[16][4];
    #pragma unroll
    for (int t = 0; t < 16; t++)
        #pragma unroll
        for (int e = 0; e < 4; e++) accS[t][e] = 0.0f;

    #pragma unroll
    for (int jn = 0; jn < 8; jn++) {
        #pragma unroll
        for (int ks = 0; ks < 2; ks++) {
            uint32_t r0, r1, r2, r3;
            ldsm_x4(r0, r1, r2, r3,
                    kb + (jn * 16 + (lid & 15)) * 80 + ks * 32 + (lid >> 4) * 16);
            uint32_t b0[2] = {r0, r2};
            uint32_t b1[2] = {r1, r3};
            mma16816(accS[jn * 2 + 0], aq[ks], b0);
            mma16816(accS[jn * 2 + 1], aq[ks], b1);
        }
    }

    // ---- softmax (rows: lid>>2 and lid>>2+8 within strip) ----
    float mx0 = -1e30f, mx1 = -1e30f;
    #pragma unroll
    for (int t = 0; t < 16; t++) {
        mx0 = fmaxf(mx0, fmaxf(accS[t][0], accS[t][1]));
        mx1 = fmaxf(mx1, fmaxf(accS[t][2], accS[t][3]));
    }
    mx0 = fmaxf(mx0, __shfl_xor_sync(0xffffffffu, mx0, 1));
    mx0 = fmaxf(mx0, __shfl_xor_sync(0xffffffffu, mx0, 2));
    mx1 = fmaxf(mx1, __shfl_xor_sync(0xffffffffu, mx1, 1));
    mx1 = fmaxf(mx1, __shfl_xor_sync(0xffffffffu, mx1, 2));

    float l0 = 0.0f, l1 = 0.0f;
    #pragma unroll
    for (int t = 0; t < 16; t++) {
        accS[t][0] = __expf((accS[t][0] - mx0) * ATTN_SCALE);
        accS[t][1] = __expf((accS[t][1] - mx0) * ATTN_SCALE);
        accS[t][2] = __expf((accS[t][2] - mx1) * ATTN_SCALE);
        accS[t][3] = __expf((accS[t][3] - mx1) * ATTN_SCALE);
        l0 += accS[t][0] + accS[t][1];
        l1 += accS[t][2] + accS[t][3];
    }
    l0 += __shfl_xor_sync(0xffffffffu, l0, 1);
    l0 += __shfl_xor_sync(0xffffffffu, l0, 2);
    l1 += __shfl_xor_sync(0xffffffffu, l1, 1);
    l1 += __shfl_xor_sync(0xffffffffu, l1, 2);
    float inv0 = 1.0f / l0;
    float inv1 = 1.0f / l1;

    // ---- O = P V (A-frags from accS; V via ldmatrix.trans) ----
    float accO[4][4];
    #pragma unroll
    for (int t = 0; t < 4; t++)
        #pragma unroll
        for (int e = 0; e < 4; e++) accO[t][e] = 0.0f;

    const uint32_t vrow = (lid & 7) + ((lid >> 3) & 1) * 8;
    #pragma unroll
    for (int kc = 0; kc < 8; kc++) {
        uint32_t ap[4];
        ap[0] = packbf2(accS[2 * kc][0],     accS[2 * kc][1]);
        ap[1] = packbf2(accS[2 * kc][2],     accS[2 * kc][3]);
        ap[2] = packbf2(accS[2 * kc + 1][0], accS[2 * kc + 1][1]);
        ap[3] = packbf2(accS[2 * kc + 1][2], accS[2 * kc + 1][3]);
        #pragma unroll
        for (int dh = 0; dh < 2; dh++) {
            uint32_t r0, r1, r2, r3;
            ldsm_x4_t(r0, r1, r2, r3,
                      vb + (kc * 16 + vrow) * 80 + dh * 32 + (lid >> 4) * 16);
            uint32_t b0[2] = {r0, r1};
            uint32_t b1[2] = {r2, r3};
            mma16816(accO[dh * 2 + 0], ap, b0);
            mma16816(accO[dh * 2 + 1], ap, b1);
        }
    }

    // ---- scatter output (bf16) ----
    #pragma unroll
    for (int half = 0; half < 2; half++) {
        int r = m0 + (lid >> 2) + half * 8;
        int ordr = order[p * KBLK + r];
        float inv = half ? inv1 : inv0;
        __nv_bfloat16* op = out + (size_t)ordr * C_DIM + h * D_HEAD;
        #pragma unroll
        for (int nt = 0; nt < 4; nt++) {
            int col = nt * 8 + (lid & 3) * 2;
            *(uint32_t*)(op + col) =
                packbf2(accO[nt][half * 2 + 0] * inv, accO[nt][half * 2 + 1] * inv);
        }
    }
}

// ---------------- launch ----------------
extern "C" void kernel_launch(void* const* d_in, const int* in_sizes, int n_in,
                              void* d_out, int out_size)
{
    const float* feat   = (const float*)d_in[0];
    const int*   order  = (const int*)  d_in[1];
    const float* qkv_w  = (const float*)d_in[3];
    const float* qkv_b  = (const float*)d_in[4];
    const float* proj_w = (const float*)d_in[5];
    const float* proj_b = (const float*)d_in[6];
    const float* ln1_g  = (const float*)d_in[7];
    const float* ln1_b  = (const float*)d_in[8];
    const float* ln2_g  = (const float*)d_in[9];
    const float* ln2_b  = (const float*)d_in[10];
    const float* w1     = (const float*)d_in[11];
    const float* b1     = (const float*)d_in[12];
    const float* w2     = (const float*)d_in[13];
    const float* b2     = (const float*)d_in[14];
    float* out = (float*)d_out;

    __nv_bfloat16 *x, *qkvb, *attn, *hbuf, *qkvw, *projw, *w1b, *w2b;
    float *x2;
    cudaGetSymbolAddress((void**)&x,     g_x);
    cudaGetSymbolAddress((void**)&qkvb,  g_qkv);
    cudaGetSymbolAddress((void**)&attn,  g_attn);
    cudaGetSymbolAddress((void**)&x2,    g_x2);
    cudaGetSymbolAddress((void**)&hbuf,  g_h);
    cudaGetSymbolAddress((void**)&qkvw,  g_qkvw);
    cudaGetSymbolAddress((void**)&projw, g_projw);
    cudaGetSymbolAddress((void**)&w1b,   g_w1);
    cudaGetSymbolAddress((void**)&w2b,   g_w2);

    cudaFuncSetAttribute(mma_gemm_kernel<EPI_BIAS, __nv_bfloat16, 256>,
                         cudaFuncAttributeMaxDynamicSharedMemorySize, GEMM_SMEM);
    cudaFuncSetAttribute(mma_gemm_kernel<EPI_RES, float, 256>,
                         cudaFuncAttributeMaxDynamicSharedMemorySize, GEMM_SMEM);
    cudaFuncSetAttribute(mma_gemm_kernel<EPI_GELU, __nv_bfloat16, 256>,
                         cudaFuncAttributeMaxDynamicSharedMemorySize, GEMM_SMEM);
    cudaFuncSetAttribute(mma_gemm_kernel<EPI_RES, float, 1024>,
                         cudaFuncAttributeMaxDynamicSharedMemorySize, GEMM_SMEM);

    // 0. weights fp32 -> bf16 (single kernel)
    cvt_all_kernel<<<512, 256>>>(qkv_w, qkvw, 3 * C_DIM * C_DIM,
                                 proj_w, projw, C_DIM * C_DIM,
                                 w1, w1b, HID_DIM * C_DIM,
                                 w2, w2b, C_DIM * HID_DIM);

    // 1. LN1 -> bf16
    ln_kernel<<<N_TOK / 8, 256>>>(feat, ln1_g, ln1_b, x);
    // 2. QKV = x @ qkv_w^T + qkv_b  (bf16 out)
    mma_gemm_kernel<EPI_BIAS, __nv_bfloat16, 256><<<dim3(6, N_TOK / 128), 256, GEMM_SMEM>>>(
        x, qkvw, qkv_b, nullptr, qkvb, 3 * C_DIM);
    // 3. block attention (HMMA, gather/scatter via order), bf16 out
    attn_mma_kernel<<<dim3(NB, H_HEADS), 256>>>(qkvb, order, attn);
    // 4. x2 = feat + attn @ proj_w^T + proj_b   (fp32 out)
    mma_gemm_kernel<EPI_RES, float, 256><<<dim3(2, N_TOK / 128), 256, GEMM_SMEM>>>(
        attn, projw, proj_b, feat, x2, C_DIM);
    // 5. LN2 -> bf16 (reuse x)
    ln_kernel<<<N_TOK / 8, 256>>>(x2, ln2_g, ln2_b, x);
    // 6. h = gelu(x @ w1^T + b1)  (bf16 out)
    mma_gemm_kernel<EPI_GELU, __nv_bfloat16, 256><<<dim3(8, N_TOK / 128), 256, GEMM_SMEM>>>(
        x, w1b, b1, nullptr, hbuf, HID_DIM);
    // 7. out = x2 + h @ w2^T + b2  (fp32 out)
    mma_gemm_kernel<EPI_RES, float, 1024><<<dim3(2, N_TOK / 128), 256, GEMM_SMEM>>>(
        hbuf, w2b, b2, x2, out, C_DIM);
}